// round 6
// baseline (speedup 1.0000x reference)
#include <cuda_runtime.h>
#include <cuda_bf16.h>
#include <cstdint>
#include <cstddef>

// ---------------------------------------------------------------------------
// MinGRU (2 layers), B=8, S=8192, DIN=DH=256.
//   gh = x @ W^T + b; a = sigmoid(-gate); v = sigmoid(gate)*g(hidden)
//   h_t = a_t*h_{t-1} + v_t, h0 = 0.5  (linear-space equivalent of reference)
// fp32 GEMM emulated with 3 bf16 mma.sync products: Ahi*Whi + Ahi*Wlo + Alo*Whi.
// R5: B (hi+lo) fully SMEM-resident; single K-sweep issuing all 3 products per
//     k-slice (MMA:LDSM 4:1); A streamed in BK=32 chunks, 3 buffers, 8 barriers.
// ---------------------------------------------------------------------------

#define M_ROWS   65536
#define KDIM     256
#define BATCH    8
#define SEQ      8192
#define NCH      64
#define CHLEN    128
#define OUT1_ELEMS 16777216

#define STAGES   3
#define BK       32
#define A_PITCH  40                      // bf16 elems per A SMEM row (128B+16B)
#define A_STAGE  (128 * A_PITCH)         // elems per half (hi or lo) per stage
#define B_PITCH  264                     // bf16 elems per B SMEM row (512B+16B)
#define B_HALF   (128 * B_PITCH)
#define SMEM_BYTES ((STAGES * 2 * A_STAGE + 2 * B_HALF) * 2)   // 196608

// -------------------- scratch (device globals; no allocation) --------------
__device__ __nv_bfloat16 g_xhi[16777216];     // 32 MB  (A hi; reused as out0 hi)
__device__ __nv_bfloat16 g_xlo[16777216];     // 32 MB  (A lo; reused as out0 lo)
__device__ float2        g_av [16777216];     // 128 MB (interleaved a,v per layer)
__device__ __nv_bfloat16 g_whi[2][131072];    // W hi, interleaved rows
__device__ __nv_bfloat16 g_wlo[2][131072];    // W lo
__device__ float         g_bc [2][512];       // bias, interleaved
__device__ float2        g_agg[BATCH * NCH * 256];
__device__ float         g_h0 [BATCH * NCH * 256];

// -------------------- small helpers ----------------------------------------
__device__ __forceinline__ void cp16(void* dst, const void* src) {
    uint32_t d = (uint32_t)__cvta_generic_to_shared(dst);
    asm volatile("cp.async.cg.shared.global [%0], [%1], 16;\n" :: "r"(d), "l"(src));
}
#define CP_COMMIT() asm volatile("cp.async.commit_group;\n" ::: "memory")

__device__ __forceinline__ void ldsm_x4(uint32_t (&r)[4], const void* p) {
    uint32_t a = (uint32_t)__cvta_generic_to_shared(p);
    asm volatile("ldmatrix.sync.aligned.m8n8.x4.shared.b16 {%0,%1,%2,%3}, [%4];"
                 : "=r"(r[0]), "=r"(r[1]), "=r"(r[2]), "=r"(r[3]) : "r"(a));
}

__device__ __forceinline__ void mma16816(float* c, const uint32_t* a, uint32_t b0, uint32_t b1) {
    asm volatile(
        "mma.sync.aligned.m16n8k16.row.col.f32.bf16.bf16.f32 "
        "{%0,%1,%2,%3}, {%4,%5,%6,%7}, {%8,%9}, {%0,%1,%2,%3};"
        : "+f"(c[0]), "+f"(c[1]), "+f"(c[2]), "+f"(c[3])
        : "r"(a[0]), "r"(a[1]), "r"(a[2]), "r"(a[3]), "r"(b0), "r"(b1));
}

// a = sigmoid(-gate), v = sigmoid(gate)*g(hidden)
__device__ __forceinline__ float2 av_from(float gate, float hid) {
    float e   = __expf(-fabsf(gate));
    float inv = 1.0f / (1.0f + e);
    float z, a;
    if (gate >= 0.0f) { z = inv;     a = e * inv; }
    else              { z = e * inv; a = inv;     }
    float g = (hid >= 0.0f) ? (hid + 0.5f) : (1.0f / (1.0f + __expf(-hid)));
    return make_float2(a, z * g);
}

// -------------------- conversion kernels -----------------------------------
__global__ void convert_x_kernel(const float* __restrict__ x) {
    size_t i = (size_t)blockIdx.x * blockDim.x + threadIdx.x;  // 4-elem groups
    float4 v = reinterpret_cast<const float4*>(x)[i];
    float vv[4] = {v.x, v.y, v.z, v.w};
    ushort4 hi, lo;
    unsigned short* hp = &hi.x;
    unsigned short* lp = &lo.x;
#pragma unroll
    for (int j = 0; j < 4; j++) {
        __nv_bfloat16 h = __float2bfloat16(vv[j]);
        float r = vv[j] - __bfloat162float(h);
        __nv_bfloat16 l = __float2bfloat16(r);
        hp[j] = __bfloat16_as_ushort(h);
        lp[j] = __bfloat16_as_ushort(l);
    }
    reinterpret_cast<ushort4*>(g_xhi)[i] = hi;
    reinterpret_cast<ushort4*>(g_xlo)[i] = lo;
}

// interleave W rows: dest row 2d = gate_d (src row d), 2d+1 = hidden_d (src row 256+d)
__global__ void convert_w_kernel(const float* __restrict__ W0, const float* __restrict__ W1) {
    int idx = blockIdx.x * blockDim.x + threadIdx.x;  // 0..262143
    int l = idx >> 17;
    int r = (idx >> 8) & 511;
    int k = idx & 255;
    const float* W = l ? W1 : W0;
    int src = (r & 1) ? (256 + (r >> 1)) : (r >> 1);
    float w = W[src * 256 + k];
    __nv_bfloat16 h = __float2bfloat16(w);
    g_whi[l][r * 256 + k] = h;
    g_wlo[l][r * 256 + k] = __float2bfloat16(w - __bfloat162float(h));
}

__global__ void convert_b_kernel(const float* __restrict__ b0, const float* __restrict__ b1) {
    int idx = blockIdx.x * blockDim.x + threadIdx.x;  // 0..1023
    int l = idx >> 9, n = idx & 511;
    int src = (n & 1) ? (256 + (n >> 1)) : (n >> 1);
    g_bc[l][n] = (l ? b1 : b0)[src];
}

// -------------------- GEMM + epilogue + fused pass1 -------------------------
// Block tile 128x128 (one scan chunk x 64 channels). B (hi+lo) resident in
// SMEM; A streamed in BK=32 chunks (hi+lo), 3 buffers. Per k-slice of 16:
// 12 LDSM, 48 MMA (3 emulation products, acc reuse at distance 16).
__global__ void __launch_bounds__(256, 1) gemm_kernel(int layer) {
    const __nv_bfloat16* __restrict__ Ahi = g_xhi;
    const __nv_bfloat16* __restrict__ Alo = g_xlo;
    const __nv_bfloat16* __restrict__ Whi = g_whi[layer];
    const __nv_bfloat16* __restrict__ Wlo = g_wlo[layer];
    const float* __restrict__ bc = g_bc[layer];

    extern __shared__ __align__(128) __nv_bfloat16 smem[];
    __nv_bfloat16* Asm = smem;                             // [3][2][128][A_PITCH]
    __nv_bfloat16* Bhi = smem + STAGES * 2 * A_STAGE;      // [128][B_PITCH]
    __nv_bfloat16* Blo = Bhi + B_HALF;

    const int tid  = threadIdx.x;
    const int lane = tid & 31;
    const int warp = tid >> 5;
    const int wm   = warp & 3;   // 4 warps along M (32 rows each)
    const int wn   = warp >> 2;  // 2 warps along N (64 cols each)
    const int m0   = blockIdx.y * 128;
    const int n0   = blockIdx.x * 128;

    float acc[2][8][4];
#pragma unroll
    for (int i = 0; i < 2; i++)
#pragma unroll
        for (int j = 0; j < 8; j++)
#pragma unroll
            for (int q = 0; q < 4; q++) acc[i][j][q] = 0.0f;

    // ---- resident B load (hi+lo), 32 cp16/thread ----
    {
        const __nv_bfloat16* wh = Whi + (size_t)n0 * KDIM;
        const __nv_bfloat16* wl = Wlo + (size_t)n0 * KDIM;
#pragma unroll
        for (int i = 0; i < 16; i++) {
            int idx = tid + i * 256;      // 0..4095
            int row = idx >> 5;
            int c   = (idx & 31) * 8;
            cp16(Bhi + row * B_PITCH + c, wh + (size_t)row * KDIM + c);
            cp16(Blo + row * B_PITCH + c, wl + (size_t)row * KDIM + c);
        }
    }
    CP_COMMIT();

    auto loadA = [&](int it) {
        int buf = it % STAGES;
        __nv_bfloat16* ah = Asm + buf * 2 * A_STAGE;
        __nv_bfloat16* al = ah + A_STAGE;
        int kb = it * BK;
#pragma unroll
        for (int i = 0; i < 2; i++) {
            int idx = tid + i * 256;      // 0..511
            int row = idx >> 2;
            int c   = (idx & 3) * 8;
            cp16(ah + row * A_PITCH + c, Ahi + (size_t)(m0 + row) * KDIM + kb + c);
            cp16(al + row * A_PITCH + c, Alo + (size_t)(m0 + row) * KDIM + kb + c);
        }
    };

    loadA(0); CP_COMMIT();
    loadA(1); CP_COMMIT();

    for (int it = 0; it < 8; ++it) {
        if (it == 7) asm volatile("cp.async.wait_group 0;\n" ::: "memory");
        else         asm volatile("cp.async.wait_group 1;\n" ::: "memory");
        __syncthreads();
        if (it + 2 < 8) { loadA(it + 2); CP_COMMIT(); }

        int buf = it % STAGES;
        const __nv_bfloat16* ah = Asm + buf * 2 * A_STAGE;
        const __nv_bfloat16* al = ah + A_STAGE;
#pragma unroll
        for (int ks = 0; ks < 2; ++ks) {
            int k0  = ks * 16;                    // within chunk
            int kg  = it * BK + k0;               // within full K (for B)
            uint32_t afh[2][4], afl[2][4];
#pragma unroll
            for (int mi = 0; mi < 2; mi++) {
                int r  = wm * 32 + mi * 16 + (lane & 15);
                int cc = k0 + ((lane & 16) ? 8 : 0);
                ldsm_x4(afh[mi], ah + r * A_PITCH + cc);
                ldsm_x4(afl[mi], al + r * A_PITCH + cc);
            }
            uint32_t bqh[4][4], bql[4][4];
#pragma unroll
            for (int nj = 0; nj < 4; nj++) {
                int r  = wn * 64 + nj * 16 + ((lane & 16) ? 8 : 0) + (lane & 7);
                int cc = kg + ((lane & 8) ? 8 : 0);
                ldsm_x4(bqh[nj], Bhi + r * B_PITCH + cc);
                ldsm_x4(bql[nj], Blo + r * B_PITCH + cc);
            }
            // product 1: Ahi * Whi
#pragma unroll
            for (int mi = 0; mi < 2; mi++)
#pragma unroll
                for (int ni = 0; ni < 8; ni++)
                    mma16816(acc[mi][ni], afh[mi], bqh[ni >> 1][(ni & 1) * 2],
                             bqh[ni >> 1][(ni & 1) * 2 + 1]);
            // product 2: Ahi * Wlo
#pragma unroll
            for (int mi = 0; mi < 2; mi++)
#pragma unroll
                for (int ni = 0; ni < 8; ni++)
                    mma16816(acc[mi][ni], afh[mi], bql[ni >> 1][(ni & 1) * 2],
                             bql[ni >> 1][(ni & 1) * 2 + 1]);
            // product 3: Alo * Whi
#pragma unroll
            for (int mi = 0; mi < 2; mi++)
#pragma unroll
                for (int ni = 0; ni < 8; ni++)
                    mma16816(acc[mi][ni], afl[mi], bqh[ni >> 1][(ni & 1) * 2],
                             bqh[ni >> 1][(ni & 1) * 2 + 1]);
        }
    }

    // ---------------- epilogue + fused scan pass1 ----------------
    __syncthreads();            // mainloop fully done; smem now reusable
    float2* av_sm = reinterpret_cast<float2*>(smem);   // [128][64] = 64KB

    const int tig = lane & 3;
    const int grp = lane >> 2;
#pragma unroll
    for (int mi = 0; mi < 2; mi++) {
        int s0 = wm * 32 + mi * 16 + grp;              // local row 0..127
#pragma unroll
        for (int ni = 0; ni < 8; ni++) {
            int col = n0 + wn * 64 + ni * 8 + tig * 2; // global interleaved col
            int chl = wn * 32 + ni * 4 + tig;          // local channel 0..63
            int d   = col >> 1;
            float bg = bc[col];
            float bh = bc[col + 1];
            float2 p0 = av_from(acc[mi][ni][0] + bg, acc[mi][ni][1] + bh);
            float2 p1 = av_from(acc[mi][ni][2] + bg, acc[mi][ni][3] + bh);
            g_av[(size_t)(m0 + s0) * 256 + d]     = p0;
            g_av[(size_t)(m0 + s0 + 8) * 256 + d] = p1;
            av_sm[s0 * 64 + chl]       = p0;
            av_sm[(s0 + 8) * 64 + chl] = p1;
        }
    }
    __syncthreads();
    if (tid < 64) {                                    // chunk reduction (pass1)
        const int b  = m0 >> 13;
        const int ck = (m0 >> 7) & 63;
        float A = 1.0f, V = 0.0f;
#pragma unroll 8
        for (int s = 0; s < CHLEN; s++) {
            float2 t = av_sm[s * 64 + tid];
            V = fmaf(t.x, V, t.y);
            A *= t.x;
        }
        g_agg[(b * NCH + ck) * 256 + (n0 >> 1) + tid] = make_float2(A, V);
    }
}

// -------------------- chunked scan -----------------------------------------
// combine: sequential over NCH chunk aggregates -> per-chunk starting h0
__global__ void scan_combine() {
    int b = blockIdx.x, d = threadIdx.x;
    float h = 0.5f;
#pragma unroll
    for (int c = 0; c < NCH; c++) {
        int i = (b * NCH + c) * 256 + d;
        g_h0[i] = h;
        float2 t = g_agg[i];
        h = fmaf(t.x, h, t.y);
    }
}

// pass3 layer 0: write out0 directly as bf16 hi/lo split (GEMM1 operand);
// last timestep -> h[0] tail of d_out
__global__ void scan_pass3_l0(float* __restrict__ dout) {
    int b = blockIdx.x, ch = blockIdx.y, d = threadIdx.x;
    float h = g_h0[(b * NCH + ch) * 256 + d];
    size_t row0 = (size_t)b * SEQ + ch * CHLEN;
#pragma unroll 4
    for (int s = 0; s < CHLEN; s++) {
        size_t idx = (row0 + s) * 256 + d;
        float2 t = g_av[idx];
        h = fmaf(t.x, h, t.y);
        __nv_bfloat16 hi = __float2bfloat16(h);
        g_xhi[idx] = hi;
        g_xlo[idx] = __float2bfloat16(h - __bfloat162float(hi));
    }
    if (ch == NCH - 1) dout[OUT1_ELEMS + b * 256 + d] = h;
}

// pass3 layer 1: write out1 fp32; last timestep -> h[1] tail
__global__ void scan_pass3_l1(float* __restrict__ dout) {
    int b = blockIdx.x, ch = blockIdx.y, d = threadIdx.x;
    float h = g_h0[(b * NCH + ch) * 256 + d];
    size_t row0 = (size_t)b * SEQ + ch * CHLEN;
#pragma unroll 4
    for (int s = 0; s < CHLEN; s++) {
        size_t idx = (row0 + s) * 256 + d;
        float2 t = g_av[idx];
        h = fmaf(t.x, h, t.y);
        dout[idx] = h;
    }
    if (ch == NCH - 1) dout[OUT1_ELEMS + 2048 + b * 256 + d] = h;
}

// -------------------- launch -----------------------------------------------
extern "C" void kernel_launch(void* const* d_in, const int* in_sizes, int n_in,
                              void* d_out, int out_size) {
    const float* x  = (const float*)d_in[0];
    const float* W0 = (const float*)d_in[1];
    const float* b0 = (const float*)d_in[2];
    const float* W1 = (const float*)d_in[3];
    const float* b1 = (const float*)d_in[4];
    float* out = (float*)d_out;

    cudaFuncSetAttribute(gemm_kernel,
                         cudaFuncAttributeMaxDynamicSharedMemorySize, SMEM_BYTES);

    convert_x_kernel<<<16384, 256>>>(x);
    convert_w_kernel<<<1024, 256>>>(W0, W1);
    convert_b_kernel<<<4, 256>>>(b0, b1);

    dim3 ggrid(4, 512);        // x = N blocks (fast) so A-panel reuse hits L2
    dim3 sgrid(BATCH, NCH);

    gemm_kernel<<<ggrid, 256, SMEM_BYTES>>>(0);   // includes fused pass1
    scan_combine<<<BATCH, 256>>>();
    scan_pass3_l0<<<sgrid, 256>>>(out);

    gemm_kernel<<<ggrid, 256, SMEM_BYTES>>>(1);   // includes fused pass1
    scan_combine<<<BATCH, 256>>>();
    scan_pass3_l1<<<sgrid, 256>>>(out);
}

// round 7
// speedup vs baseline: 1.2045x; 1.2045x over previous
#include <cuda_runtime.h>
#include <cuda_bf16.h>
#include <cstdint>
#include <cstddef>

// ---------------------------------------------------------------------------
// MinGRU (2 layers), B=8, S=8192, DIN=DH=256.
//   gh = x @ W^T + b; a = sigmoid(-gate); v = sigmoid(gate)*g(hidden)
//   h_t = a_t*h_{t-1} + v_t, h0 = 0.5  (linear-space equivalent of reference)
// fp32 GEMM emulated with 3 bf16 mma.sync products: Ahi*Whi + Ahi*Wlo + Alo*Whi.
// R6: stages carry (A, B1, B2); its 0..7 share one Ahi fragment across two
//     products (Whi+Wlo); its 8..15 do Alo*Whi. 2 CTAs/SM preserved (92KB).
// ---------------------------------------------------------------------------

#define M_ROWS   65536
#define KDIM     256
#define BATCH    8
#define SEQ      8192
#define NCH      64
#define CHLEN    128
#define OUT1_ELEMS 16777216

#define STAGES     3
#define BK         32
#define A_PITCH    40                        // bf16 elems per SMEM row
#define SLOT_ELEMS (128 * A_PITCH)           // 5120 elems = 10240 B
#define STAGE_ELEMS (3 * SLOT_ELEMS)         // A, B1, B2
#define SMEM_BYTES (STAGES * STAGE_ELEMS * 2)   // 92160

// -------------------- scratch (device globals; no allocation) --------------
__device__ __nv_bfloat16 g_xhi[16777216];     // 32 MB  (A hi; reused as out0 hi)
__device__ __nv_bfloat16 g_xlo[16777216];     // 32 MB  (A lo; reused as out0 lo)
__device__ float2        g_av [16777216];     // 128 MB (interleaved a,v per layer)
__device__ __nv_bfloat16 g_whi[2][131072];    // W hi, interleaved rows
__device__ __nv_bfloat16 g_wlo[2][131072];    // W lo
__device__ float         g_bc [2][512];       // bias, interleaved
__device__ float2        g_agg[BATCH * NCH * 256];
__device__ float         g_h0 [BATCH * NCH * 256];

// -------------------- small helpers ----------------------------------------
__device__ __forceinline__ void cp16(void* dst, const void* src) {
    uint32_t d = (uint32_t)__cvta_generic_to_shared(dst);
    asm volatile("cp.async.cg.shared.global [%0], [%1], 16;\n" :: "r"(d), "l"(src));
}
#define CP_COMMIT() asm volatile("cp.async.commit_group;\n" ::: "memory")

__device__ __forceinline__ void ldsm_x4(uint32_t (&r)[4], const void* p) {
    uint32_t a = (uint32_t)__cvta_generic_to_shared(p);
    asm volatile("ldmatrix.sync.aligned.m8n8.x4.shared.b16 {%0,%1,%2,%3}, [%4];"
                 : "=r"(r[0]), "=r"(r[1]), "=r"(r[2]), "=r"(r[3]) : "r"(a));
}

__device__ __forceinline__ void mma16816(float* c, const uint32_t* a, uint32_t b0, uint32_t b1) {
    asm volatile(
        "mma.sync.aligned.m16n8k16.row.col.f32.bf16.bf16.f32 "
        "{%0,%1,%2,%3}, {%4,%5,%6,%7}, {%8,%9}, {%0,%1,%2,%3};"
        : "+f"(c[0]), "+f"(c[1]), "+f"(c[2]), "+f"(c[3])
        : "r"(a[0]), "r"(a[1]), "r"(a[2]), "r"(a[3]), "r"(b0), "r"(b1));
}

// a = sigmoid(-gate), v = sigmoid(gate)*g(hidden)
__device__ __forceinline__ float2 av_from(float gate, float hid) {
    float e   = __expf(-fabsf(gate));
    float inv = 1.0f / (1.0f + e);
    float z, a;
    if (gate >= 0.0f) { z = inv;     a = e * inv; }
    else              { z = e * inv; a = inv;     }
    float g = (hid >= 0.0f) ? (hid + 0.5f) : (1.0f / (1.0f + __expf(-hid)));
    return make_float2(a, z * g);
}

// -------------------- conversion kernels -----------------------------------
__global__ void convert_x_kernel(const float* __restrict__ x) {
    size_t i = (size_t)blockIdx.x * blockDim.x + threadIdx.x;  // 4-elem groups
    float4 v = reinterpret_cast<const float4*>(x)[i];
    float vv[4] = {v.x, v.y, v.z, v.w};
    ushort4 hi, lo;
    unsigned short* hp = &hi.x;
    unsigned short* lp = &lo.x;
#pragma unroll
    for (int j = 0; j < 4; j++) {
        __nv_bfloat16 h = __float2bfloat16(vv[j]);
        float r = vv[j] - __bfloat162float(h);
        __nv_bfloat16 l = __float2bfloat16(r);
        hp[j] = __bfloat16_as_ushort(h);
        lp[j] = __bfloat16_as_ushort(l);
    }
    reinterpret_cast<ushort4*>(g_xhi)[i] = hi;
    reinterpret_cast<ushort4*>(g_xlo)[i] = lo;
}

// interleave W rows: dest row 2d = gate_d (src row d), 2d+1 = hidden_d (src row 256+d)
__global__ void convert_w_kernel(const float* __restrict__ W0, const float* __restrict__ W1) {
    int idx = blockIdx.x * blockDim.x + threadIdx.x;  // 0..262143
    int l = idx >> 17;
    int r = (idx >> 8) & 511;
    int k = idx & 255;
    const float* W = l ? W1 : W0;
    int src = (r & 1) ? (256 + (r >> 1)) : (r >> 1);
    float w = W[src * 256 + k];
    __nv_bfloat16 h = __float2bfloat16(w);
    g_whi[l][r * 256 + k] = h;
    g_wlo[l][r * 256 + k] = __float2bfloat16(w - __bfloat162float(h));
}

__global__ void convert_b_kernel(const float* __restrict__ b0, const float* __restrict__ b1) {
    int idx = blockIdx.x * blockDim.x + threadIdx.x;  // 0..1023
    int l = idx >> 9, n = idx & 511;
    int src = (n & 1) ? (256 + (n >> 1)) : (n >> 1);
    g_bc[l][n] = (l ? b1 : b0)[src];
}

// -------------------- GEMM + epilogue + fused pass1 -------------------------
// Block tile 128x128 (one scan chunk x 64 channels).
// its 0..7 : stage = (Ahi[kb], Whi[kb], Wlo[kb]) -> af shared by two products
// its 8..15: stage = (Alo[kb], Whi[kb])          -> one product
__global__ void __launch_bounds__(256, 2) gemm_kernel(int layer) {
    const __nv_bfloat16* __restrict__ Ahi = g_xhi;
    const __nv_bfloat16* __restrict__ Alo = g_xlo;
    const __nv_bfloat16* __restrict__ Whi = g_whi[layer];
    const __nv_bfloat16* __restrict__ Wlo = g_wlo[layer];
    const float* __restrict__ bc = g_bc[layer];

    extern __shared__ __align__(128) __nv_bfloat16 smem[];

    const int tid  = threadIdx.x;
    const int lane = tid & 31;
    const int warp = tid >> 5;
    const int wm   = warp & 3;   // 4 warps along M (32 rows each)
    const int wn   = warp >> 2;  // 2 warps along N (64 cols each)
    const int m0   = blockIdx.y * 128;
    const int n0   = blockIdx.x * 128;

    float acc[2][8][4];
#pragma unroll
    for (int i = 0; i < 2; i++)
#pragma unroll
        for (int j = 0; j < 8; j++)
#pragma unroll
            for (int q = 0; q < 4; q++) acc[i][j][q] = 0.0f;

    const __nv_bfloat16* whb = Whi + (size_t)n0 * KDIM;
    const __nv_bfloat16* wlb = Wlo + (size_t)n0 * KDIM;

    auto load_tile = [&](int it) {
        int buf = it % STAGES;
        __nv_bfloat16* st = smem + buf * STAGE_ELEMS;
        const __nv_bfloat16* gA = (it < 8) ? Ahi : Alo;
        int kb = (it & 7) * BK;
#pragma unroll
        for (int i = 0; i < 2; i++) {
            int idx = tid * 2 + i;          // 0..511
            int row = idx >> 2;
            int c   = (idx & 3) * 8;
            cp16(st + row * A_PITCH + c, gA + (size_t)(m0 + row) * KDIM + kb + c);
            cp16(st + SLOT_ELEMS + row * A_PITCH + c,
                 whb + (size_t)row * KDIM + kb + c);
            if (it < 8)
                cp16(st + 2 * SLOT_ELEMS + row * A_PITCH + c,
                     wlb + (size_t)row * KDIM + kb + c);
        }
    };

    load_tile(0); CP_COMMIT();
    load_tile(1); CP_COMMIT();

    for (int it = 0; it < 16; ++it) {
        if (it == 15) asm volatile("cp.async.wait_group 0;\n" ::: "memory");
        else          asm volatile("cp.async.wait_group 1;\n" ::: "memory");
        __syncthreads();
        if (it + 2 < 16) load_tile(it + 2);
        CP_COMMIT();

        const __nv_bfloat16* st = smem + (it % STAGES) * STAGE_ELEMS;
        const bool dual = (it < 8);
#pragma unroll
        for (int ks = 0; ks < 2; ++ks) {
            int k0 = ks * 16;
            uint32_t af[2][4];
#pragma unroll
            for (int mi = 0; mi < 2; mi++) {
                int r  = wm * 32 + mi * 16 + (lane & 15);
                int cc = k0 + ((lane & 16) ? 8 : 0);
                ldsm_x4(af[mi], st + r * A_PITCH + cc);
            }
            uint32_t bq1[4][4], bq2[4][4];
#pragma unroll
            for (int nj = 0; nj < 4; nj++) {
                int r  = wn * 64 + nj * 16 + ((lane & 16) ? 8 : 0) + (lane & 7);
                int cc = k0 + ((lane & 8) ? 8 : 0);
                ldsm_x4(bq1[nj], st + SLOT_ELEMS + r * A_PITCH + cc);
                if (dual)
                    ldsm_x4(bq2[nj], st + 2 * SLOT_ELEMS + r * A_PITCH + cc);
            }
#pragma unroll
            for (int mi = 0; mi < 2; mi++)
#pragma unroll
                for (int ni = 0; ni < 8; ni++)
                    mma16816(acc[mi][ni], af[mi], bq1[ni >> 1][(ni & 1) * 2],
                             bq1[ni >> 1][(ni & 1) * 2 + 1]);
            if (dual) {
#pragma unroll
                for (int mi = 0; mi < 2; mi++)
#pragma unroll
                    for (int ni = 0; ni < 8; ni++)
                        mma16816(acc[mi][ni], af[mi], bq2[ni >> 1][(ni & 1) * 2],
                                 bq2[ni >> 1][(ni & 1) * 2 + 1]);
            }
        }
    }

    // ---------------- epilogue + fused scan pass1 ----------------
    __syncthreads();            // mainloop fully done; smem now reusable
    float2* av_sm = reinterpret_cast<float2*>(smem);   // [128][64] = 64KB

    const int tig = lane & 3;
    const int grp = lane >> 2;
#pragma unroll
    for (int mi = 0; mi < 2; mi++) {
        int s0 = wm * 32 + mi * 16 + grp;              // local row 0..127
#pragma unroll
        for (int ni = 0; ni < 8; ni++) {
            int col = n0 + wn * 64 + ni * 8 + tig * 2; // global interleaved col
            int chl = wn * 32 + ni * 4 + tig;          // local channel 0..63
            int d   = col >> 1;
            float bg = bc[col];
            float bh = bc[col + 1];
            float2 p0 = av_from(acc[mi][ni][0] + bg, acc[mi][ni][1] + bh);
            float2 p1 = av_from(acc[mi][ni][2] + bg, acc[mi][ni][3] + bh);
            g_av[(size_t)(m0 + s0) * 256 + d]     = p0;
            g_av[(size_t)(m0 + s0 + 8) * 256 + d] = p1;
            av_sm[s0 * 64 + chl]       = p0;
            av_sm[(s0 + 8) * 64 + chl] = p1;
        }
    }
    __syncthreads();
    if (tid < 64) {                                    // chunk reduction (pass1)
        const int b  = m0 >> 13;
        const int ck = (m0 >> 7) & 63;
        float A = 1.0f, V = 0.0f;
#pragma unroll 8
        for (int s = 0; s < CHLEN; s++) {
            float2 t = av_sm[s * 64 + tid];
            V = fmaf(t.x, V, t.y);
            A *= t.x;
        }
        g_agg[(b * NCH + ck) * 256 + (n0 >> 1) + tid] = make_float2(A, V);
    }
}

// -------------------- chunked scan -----------------------------------------
// combine: sequential over NCH chunk aggregates -> per-chunk starting h0.
// Loads batched 8-wide so the serial FMA chain isn't L2-latency bound.
__global__ void scan_combine() {
    int b = blockIdx.x, d = threadIdx.x;
    float h = 0.5f;
    for (int c0 = 0; c0 < NCH; c0 += 8) {
        float2 t[8];
#pragma unroll
        for (int j = 0; j < 8; j++)
            t[j] = g_agg[(b * NCH + c0 + j) * 256 + d];
#pragma unroll
        for (int j = 0; j < 8; j++) {
            g_h0[(b * NCH + c0 + j) * 256 + d] = h;
            h = fmaf(t[j].x, h, t[j].y);
        }
    }
}

// pass3 layer 0: write out0 directly as bf16 hi/lo split (GEMM1 operand);
// last timestep -> h[0] tail of d_out
__global__ void scan_pass3_l0(float* __restrict__ dout) {
    int b = blockIdx.x, ch = blockIdx.y, d = threadIdx.x;
    float h = g_h0[(b * NCH + ch) * 256 + d];
    size_t row0 = (size_t)b * SEQ + ch * CHLEN;
#pragma unroll 8
    for (int s = 0; s < CHLEN; s++) {
        size_t idx = (row0 + s) * 256 + d;
        float2 t = g_av[idx];
        h = fmaf(t.x, h, t.y);
        __nv_bfloat16 hi = __float2bfloat16(h);
        g_xhi[idx] = hi;
        g_xlo[idx] = __float2bfloat16(h - __bfloat162float(hi));
    }
    if (ch == NCH - 1) dout[OUT1_ELEMS + b * 256 + d] = h;
}

// pass3 layer 1: write out1 fp32; last timestep -> h[1] tail
__global__ void scan_pass3_l1(float* __restrict__ dout) {
    int b = blockIdx.x, ch = blockIdx.y, d = threadIdx.x;
    float h = g_h0[(b * NCH + ch) * 256 + d];
    size_t row0 = (size_t)b * SEQ + ch * CHLEN;
#pragma unroll 8
    for (int s = 0; s < CHLEN; s++) {
        size_t idx = (row0 + s) * 256 + d;
        float2 t = g_av[idx];
        h = fmaf(t.x, h, t.y);
        dout[idx] = h;
    }
    if (ch == NCH - 1) dout[OUT1_ELEMS + 2048 + b * 256 + d] = h;
}

// -------------------- launch -----------------------------------------------
extern "C" void kernel_launch(void* const* d_in, const int* in_sizes, int n_in,
                              void* d_out, int out_size) {
    const float* x  = (const float*)d_in[0];
    const float* W0 = (const float*)d_in[1];
    const float* b0 = (const float*)d_in[2];
    const float* W1 = (const float*)d_in[3];
    const float* b1 = (const float*)d_in[4];
    float* out = (float*)d_out;

    cudaFuncSetAttribute(gemm_kernel,
                         cudaFuncAttributeMaxDynamicSharedMemorySize, SMEM_BYTES);

    convert_x_kernel<<<16384, 256>>>(x);
    convert_w_kernel<<<1024, 256>>>(W0, W1);
    convert_b_kernel<<<4, 256>>>(b0, b1);

    dim3 ggrid(4, 512);        // x = N blocks (fast) so A-panel reuse hits L2
    dim3 sgrid(BATCH, NCH);

    gemm_kernel<<<ggrid, 256, SMEM_BYTES>>>(0);   // includes fused pass1
    scan_combine<<<BATCH, 256>>>();
    scan_pass3_l0<<<sgrid, 256>>>(out);

    gemm_kernel<<<ggrid, 256, SMEM_BYTES>>>(1);   // includes fused pass1
    scan_combine<<<BATCH, 256>>>();
    scan_pass3_l1<<<sgrid, 256>>>(out);
}

// round 9
// speedup vs baseline: 1.4267x; 1.1845x over previous
#include <cuda_runtime.h>
#include <cuda_bf16.h>
#include <cstdint>
#include <cstddef>

// ---------------------------------------------------------------------------
// MinGRU (2 layers), B=8, S=8192, DIN=DH=256.
//   gh = x @ W^T + b; a = sigmoid(-gate); v = sigmoid(gate)*g(hidden)
//   h_t = a_t*h_{t-1} + v_t, h0 = 0.5  (linear-space equivalent of reference)
// fp32 GEMM emulated with 3 bf16 mma.sync products: Ahi*Whi + Ahi*Wlo + Alo*Whi.
// R8: unified-chunk stages {Ahi,Alo,Whi,Wlo} @ BK=32, pitch 32 with quad-XOR
//     swizzle (p' = p ^ ((row>>1)&3)); 3 stages, 8 iterations, all 3 products
//     per chunk; 96KB SMEM -> 2 CTAs/SM. Parallel in-CTA pass1 epilogue.
// ---------------------------------------------------------------------------

#define M_ROWS   65536
#define KDIM     256
#define BATCH    8
#define SEQ      8192
#define NCH      64
#define CHLEN    128
#define OUT1_ELEMS 16777216

#define STAGES     3
#define BK         32
#define SLOT_ELEMS (128 * 32)                // 4096 elems = 8192 B (no padding)
#define STAGE_ELEMS (4 * SLOT_ELEMS)         // Ahi, Alo, Whi, Wlo
#define SMEM_BYTES (STAGES * STAGE_ELEMS * 2)   // 98304

// swizzled element offset within a slot; col is bf16 elem 0..31, col%8==0 use
__device__ __forceinline__ int swoff(int row, int col) {
    return row * 32 + ((((col >> 3) ^ ((row >> 1) & 3)) << 3) | (col & 7));
}

// -------------------- scratch (device globals; no allocation) --------------
__device__ __nv_bfloat16 g_xhi[16777216];     // 32 MB  (A hi; reused as out0 hi)
__device__ __nv_bfloat16 g_xlo[16777216];     // 32 MB  (A lo; reused as out0 lo)
__device__ float2        g_av [16777216];     // 128 MB (interleaved a,v per layer)
__device__ __nv_bfloat16 g_whi[2][131072];    // W hi, interleaved rows
__device__ __nv_bfloat16 g_wlo[2][131072];    // W lo
__device__ float         g_bc [2][512];       // bias, interleaved
__device__ float2        g_agg[BATCH * NCH * 256];
__device__ float         g_h0 [BATCH * NCH * 256];

// -------------------- small helpers ----------------------------------------
__device__ __forceinline__ void cp16(void* dst, const void* src) {
    uint32_t d = (uint32_t)__cvta_generic_to_shared(dst);
    asm volatile("cp.async.cg.shared.global [%0], [%1], 16;\n" :: "r"(d), "l"(src));
}
#define CP_COMMIT() asm volatile("cp.async.commit_group;\n" ::: "memory")

__device__ __forceinline__ void ldsm_x4(uint32_t (&r)[4], const void* p) {
    uint32_t a = (uint32_t)__cvta_generic_to_shared(p);
    asm volatile("ldmatrix.sync.aligned.m8n8.x4.shared.b16 {%0,%1,%2,%3}, [%4];"
                 : "=r"(r[0]), "=r"(r[1]), "=r"(r[2]), "=r"(r[3]) : "r"(a));
}

__device__ __forceinline__ void mma16816(float* c, const uint32_t* a, uint32_t b0, uint32_t b1) {
    asm volatile(
        "mma.sync.aligned.m16n8k16.row.col.f32.bf16.bf16.f32 "
        "{%0,%1,%2,%3}, {%4,%5,%6,%7}, {%8,%9}, {%0,%1,%2,%3};"
        : "+f"(c[0]), "+f"(c[1]), "+f"(c[2]), "+f"(c[3])
        : "r"(a[0]), "r"(a[1]), "r"(a[2]), "r"(a[3]), "r"(b0), "r"(b1));
}

// a = sigmoid(-gate), v = sigmoid(gate)*g(hidden)
__device__ __forceinline__ float2 av_from(float gate, float hid) {
    float e   = __expf(-fabsf(gate));
    float inv = 1.0f / (1.0f + e);
    float z, a;
    if (gate >= 0.0f) { z = inv;     a = e * inv; }
    else              { z = e * inv; a = inv;     }
    float g = (hid >= 0.0f) ? (hid + 0.5f) : (1.0f / (1.0f + __expf(-hid)));
    return make_float2(a, z * g);
}

// -------------------- conversion kernels -----------------------------------
__global__ void convert_x_kernel(const float* __restrict__ x) {
    size_t i = (size_t)blockIdx.x * blockDim.x + threadIdx.x;  // 4-elem groups
    float4 v = reinterpret_cast<const float4*>(x)[i];
    float vv[4] = {v.x, v.y, v.z, v.w};
    ushort4 hi, lo;
    unsigned short* hp = &hi.x;
    unsigned short* lp = &lo.x;
#pragma unroll
    for (int j = 0; j < 4; j++) {
        __nv_bfloat16 h = __float2bfloat16(vv[j]);
        float r = vv[j] - __bfloat162float(h);
        __nv_bfloat16 l = __float2bfloat16(r);
        hp[j] = __bfloat16_as_ushort(h);
        lp[j] = __bfloat16_as_ushort(l);
    }
    reinterpret_cast<ushort4*>(g_xhi)[i] = hi;
    reinterpret_cast<ushort4*>(g_xlo)[i] = lo;
}

// W rows interleaved (gate_d, hidden_d) + bias, one launch.
__global__ void convert_wb_kernel(const float* __restrict__ W0, const float* __restrict__ W1,
                                  const float* __restrict__ b0, const float* __restrict__ b1) {
    int idx = blockIdx.x * blockDim.x + threadIdx.x;  // 0..263167
    if (idx < 262144) {
        int l = idx >> 17;
        int r = (idx >> 8) & 511;
        int k = idx & 255;
        const float* W = l ? W1 : W0;
        int src = (r & 1) ? (256 + (r >> 1)) : (r >> 1);
        float w = W[src * 256 + k];
        __nv_bfloat16 h = __float2bfloat16(w);
        g_whi[l][r * 256 + k] = h;
        g_wlo[l][r * 256 + k] = __float2bfloat16(w - __bfloat162float(h));
    } else {
        int j = idx - 262144;                 // 0..1023
        int l = j >> 9, n = j & 511;
        int src = (n & 1) ? (256 + (n >> 1)) : (n >> 1);
        g_bc[l][n] = (l ? b1 : b0)[src];
    }
}

// -------------------- GEMM + epilogue + fused pass1 -------------------------
// Block tile 128x128 (one scan chunk x 64 channels). 8 iterations; stage c
// holds {Ahi,Alo,Whi,Wlo} for k-chunk c (swizzled); all 3 products per chunk.
__global__ void __launch_bounds__(256, 2) gemm_kernel(int layer) {
    const __nv_bfloat16* __restrict__ Ahi = g_xhi;
    const __nv_bfloat16* __restrict__ Alo = g_xlo;
    const __nv_bfloat16* __restrict__ Whi = g_whi[layer];
    const __nv_bfloat16* __restrict__ Wlo = g_wlo[layer];
    const float* __restrict__ bc = g_bc[layer];

    extern __shared__ __align__(128) __nv_bfloat16 smem[];

    const int tid  = threadIdx.x;
    const int lane = tid & 31;
    const int warp = tid >> 5;
    const int wm   = warp & 3;   // 4 warps along M (32 rows each)
    const int wn   = warp >> 2;  // 2 warps along N (64 cols each)
    const int m0   = blockIdx.y * 128;
    const int n0   = blockIdx.x * 128;

    float acc[2][8][4];
#pragma unroll
    for (int i = 0; i < 2; i++)
#pragma unroll
        for (int j = 0; j < 8; j++)
#pragma unroll
            for (int q = 0; q < 4; q++) acc[i][j][q] = 0.0f;

    const __nv_bfloat16* whb = Whi + (size_t)n0 * KDIM;
    const __nv_bfloat16* wlb = Wlo + (size_t)n0 * KDIM;

    auto load_stage = [&](int it) {
        int buf = it % STAGES;
        __nv_bfloat16* st = smem + buf * STAGE_ELEMS;
        int kb = it * BK;
#pragma unroll
        for (int i = 0; i < 2; i++) {
            int idx = tid * 2 + i;          // 0..511
            int row = idx >> 2;
            int c   = (idx & 3) * 8;
            int so  = swoff(row, c);
            size_t ga = (size_t)(m0 + row) * KDIM + kb + c;
            size_t gw = (size_t)row * KDIM + kb + c;
            cp16(st + so,                  Ahi + ga);
            cp16(st + SLOT_ELEMS + so,     Alo + ga);
            cp16(st + 2 * SLOT_ELEMS + so, whb + gw);
            cp16(st + 3 * SLOT_ELEMS + so, wlb + gw);
        }
    };

    load_stage(0); CP_COMMIT();
    load_stage(1); CP_COMMIT();

    for (int it = 0; it < 8; ++it) {
        if (it == 7) asm volatile("cp.async.wait_group 0;\n" ::: "memory");
        else         asm volatile("cp.async.wait_group 1;\n" ::: "memory");
        __syncthreads();
        if (it + 2 < 8) load_stage(it + 2);
        CP_COMMIT();

        const __nv_bfloat16* st = smem + (it % STAGES) * STAGE_ELEMS;
#pragma unroll
        for (int ks = 0; ks < 2; ++ks) {
            int k0 = ks * 16;
            int ra = wm * 32 + (lane & 15);
            int ca = k0 + ((lane & 16) ? 8 : 0);
            int rb = wn * 64 + ((lane & 16) ? 8 : 0) + (lane & 7);
            int cb = k0 + ((lane & 8) ? 8 : 0);

            uint32_t afh[2][4], afl[2][4];
#pragma unroll
            for (int mi = 0; mi < 2; mi++) {
                int so = swoff(ra + mi * 16, ca);
                ldsm_x4(afh[mi], st + so);
                ldsm_x4(afl[mi], st + SLOT_ELEMS + so);
            }
            uint32_t bqh[4][4];
#pragma unroll
            for (int nj = 0; nj < 4; nj++)
                ldsm_x4(bqh[nj], st + 2 * SLOT_ELEMS + swoff(rb + nj * 16, cb));
            // product 1: Ahi * Whi
#pragma unroll
            for (int mi = 0; mi < 2; mi++)
#pragma unroll
                for (int ni = 0; ni < 8; ni++)
                    mma16816(acc[mi][ni], afh[mi], bqh[ni >> 1][(ni & 1) * 2],
                             bqh[ni >> 1][(ni & 1) * 2 + 1]);
            // product 3: Alo * Whi  (bqh dead afterwards)
#pragma unroll
            for (int mi = 0; mi < 2; mi++)
#pragma unroll
                for (int ni = 0; ni < 8; ni++)
                    mma16816(acc[mi][ni], afl[mi], bqh[ni >> 1][(ni & 1) * 2],
                             bqh[ni >> 1][(ni & 1) * 2 + 1]);
            // product 2: Ahi * Wlo
            uint32_t bql[4][4];
#pragma unroll
            for (int nj = 0; nj < 4; nj++)
                ldsm_x4(bql[nj], st + 3 * SLOT_ELEMS + swoff(rb + nj * 16, cb));
#pragma unroll
            for (int mi = 0; mi < 2; mi++)
#pragma unroll
                for (int ni = 0; ni < 8; ni++)
                    mma16816(acc[mi][ni], afh[mi], bql[ni >> 1][(ni & 1) * 2],
                             bql[ni >> 1][(ni & 1) * 2 + 1]);
        }
    }

    // ---------------- epilogue + fused scan pass1 ----------------
    __syncthreads();            // mainloop fully done; smem now reusable
    float2* av_sm  = reinterpret_cast<float2*>(smem);            // [128][64] 64KB
    float2* red_sm = reinterpret_cast<float2*>(smem) + 128 * 64; // [4][64]  2KB

    const int tig = lane & 3;
    const int grp = lane >> 2;
#pragma unroll
    for (int mi = 0; mi < 2; mi++) {
        int s0 = wm * 32 + mi * 16 + grp;              // local row 0..127
#pragma unroll
        for (int ni = 0; ni < 8; ni++) {
            int col = n0 + wn * 64 + ni * 8 + tig * 2; // global interleaved col
            int chl = wn * 32 + ni * 4 + tig;          // local channel 0..63
            int d   = col >> 1;
            float bg = bc[col];
            float bh = bc[col + 1];
            float2 p0 = av_from(acc[mi][ni][0] + bg, acc[mi][ni][1] + bh);
            float2 p1 = av_from(acc[mi][ni][2] + bg, acc[mi][ni][3] + bh);
            g_av[(size_t)(m0 + s0) * 256 + d]     = p0;
            g_av[(size_t)(m0 + s0 + 8) * 256 + d] = p1;
            av_sm[s0 * 64 + chl]       = p0;
            av_sm[(s0 + 8) * 64 + chl] = p1;
        }
    }
    __syncthreads();
    {   // parallel pass1: 4 groups x 32-step sub-scans, then 4-way combine
        const int g = tid >> 6;          // 0..3
        const int d = tid & 63;          // channel
        float A = 1.0f, V = 0.0f;
#pragma unroll 8
        for (int s = g * 32; s < g * 32 + 32; s++) {
            float2 t = av_sm[s * 64 + d];
            V = fmaf(t.x, V, t.y);
            A *= t.x;
        }
        red_sm[g * 64 + d] = make_float2(A, V);
    }
    __syncthreads();
    if (tid < 64) {
        const int b  = m0 >> 13;
        const int ck = (m0 >> 7) & 63;
        float A = 1.0f, V = 0.0f;
#pragma unroll
        for (int g = 0; g < 4; g++) {
            float2 t = red_sm[g * 64 + tid];
            V = fmaf(t.x, V, t.y);   // V = A_g*V_prev + V_g
            A *= t.x;
        }
        g_agg[(b * NCH + ck) * 256 + (n0 >> 1) + tid] = make_float2(A, V);
    }
}

// -------------------- chunked scan -----------------------------------------
// combine: sequential over NCH chunk aggregates -> per-chunk starting h0.
__global__ void scan_combine() {
    int b = blockIdx.x, d = threadIdx.x;
    float h = 0.5f;
    for (int c0 = 0; c0 < NCH; c0 += 8) {
        float2 t[8];
#pragma unroll
        for (int j = 0; j < 8; j++)
            t[j] = g_agg[(b * NCH + c0 + j) * 256 + d];
#pragma unroll
        for (int j = 0; j < 8; j++) {
            g_h0[(b * NCH + c0 + j) * 256 + d] = h;
            h = fmaf(t[j].x, h, t[j].y);
        }
    }
}

// pass3 layer 0: write out0 directly as bf16 hi/lo split (GEMM1 operand);
// last timestep -> h[0] tail of d_out
__global__ void scan_pass3_l0(float* __restrict__ dout) {
    int b = blockIdx.x, ch = blockIdx.y, d = threadIdx.x;
    float h = g_h0[(b * NCH + ch) * 256 + d];
    size_t row0 = (size_t)b * SEQ + ch * CHLEN;
#pragma unroll 8
    for (int s = 0; s < CHLEN; s++) {
        size_t idx = (row0 + s) * 256 + d;
        float2 t = g_av[idx];
        h = fmaf(t.x, h, t.y);
        __nv_bfloat16 hi = __float2bfloat16(h);
        g_xhi[idx] = hi;
        g_xlo[idx] = __float2bfloat16(h - __bfloat162float(hi));
    }
    if (ch == NCH - 1) dout[OUT1_ELEMS + b * 256 + d] = h;
}

// pass3 layer 1: write out1 fp32; last timestep -> h[1] tail
__global__ void scan_pass3_l1(float* __restrict__ dout) {
    int b = blockIdx.x, ch = blockIdx.y, d = threadIdx.x;
    float h = g_h0[(b * NCH + ch) * 256 + d];
    size_t row0 = (size_t)b * SEQ + ch * CHLEN;
#pragma unroll 8
    for (int s = 0; s < CHLEN; s++) {
        size_t idx = (row0 + s) * 256 + d;
        float2 t = g_av[idx];
        h = fmaf(t.x, h, t.y);
        dout[idx] = h;
    }
    if (ch == NCH - 1) dout[OUT1_ELEMS + 2048 + b * 256 + d] = h;
}

// -------------------- launch -----------------------------------------------
extern "C" void kernel_launch(void* const* d_in, const int* in_sizes, int n_in,
                              void* d_out, int out_size) {
    const float* x  = (const float*)d_in[0];
    const float* W0 = (const float*)d_in[1];
    const float* b0 = (const float*)d_in[2];
    const float* W1 = (const float*)d_in[3];
    const float* b1 = (const float*)d_in[4];
    float* out = (float*)d_out;

    cudaFuncSetAttribute(gemm_kernel,
                         cudaFuncAttributeMaxDynamicSharedMemorySize, SMEM_BYTES);

    convert_x_kernel<<<16384, 256>>>(x);
    convert_wb_kernel<<<1028, 256>>>(W0, W1, b0, b1);

    dim3 ggrid(4, 512);        // x = N blocks (fast) so A-panel reuse hits L2
    dim3 sgrid(BATCH, NCH);

    gemm_kernel<<<ggrid, 256, SMEM_BYTES>>>(0);   // includes fused pass1
    scan_combine<<<BATCH, 256>>>();
    scan_pass3_l0<<<sgrid, 256>>>(out);

    gemm_kernel<<<ggrid, 256, SMEM_BYTES>>>(1);   // includes fused pass1
    scan_combine<<<BATCH, 256>>>();
    scan_pass3_l1<<<sgrid, 256>>>(out);
}